// round 2
// baseline (speedup 1.0000x reference)
#include <cuda_runtime.h>
#include <cstdint>
#include <cstddef>

#define NE 1000000
#define NN 50000

// scratch for node projections (static device globals: allowed, no runtime alloc)
__device__ float g_xs[(size_t)NN * 64];
__device__ float g_xt[(size_t)NN * 64];

__device__ __forceinline__ uint32_t f2tf(float f) {
    uint32_t r;
    asm("cvt.rna.tf32.f32 %0, %1;" : "=r"(r) : "f"(f));
    return r;
}

__device__ __forceinline__ void mma8(float c[4],
                                     uint32_t a0, uint32_t a1, uint32_t a2, uint32_t a3,
                                     uint32_t b0, uint32_t b1) {
    asm volatile(
        "mma.sync.aligned.m16n8k8.row.col.f32.tf32.tf32.f32 "
        "{%0,%1,%2,%3}, {%4,%5,%6,%7}, {%8,%9}, {%10,%11,%12,%13};\n"
        : "=f"(c[0]), "=f"(c[1]), "=f"(c[2]), "=f"(c[3])
        : "r"(a0), "r"(a1), "r"(a2), "r"(a3), "r"(b0), "r"(b1),
          "f"(c[0]), "f"(c[1]), "f"(c[2]), "f"(c[3]));
}

// jax.nn.gelu default (approximate=True): 0.5x(1+tanh(sqrt(2/pi)(x+0.044715x^3)))
__device__ __forceinline__ float gelu_tanh(float v) {
    float v3 = v * v * v;
    float u = 0.7978845608028654f * v + 0.035677408136300125f * v3;
    float e = __expf(2.0f * u);                       // tanh(u) = 1 - 2/(e^{2u}+1)
    float t = 1.0f - __fdividef(2.0f, e + 1.0f);
    return 0.5f * v * (1.0f + t);
}

// ---------------------------------------------------------------------------
// Kernel 1: node projections  XS = X@Ws^T + (bs+be),  XT = X@Wt^T + bt
// 128 nodes per block, 256 threads (8 warps x 16 rows), K=128, N=64
// ---------------------------------------------------------------------------
__global__ __launch_bounds__(256)
void node_proj_kernel(const float* __restrict__ x,
                      const float* __restrict__ Ws, const float* __restrict__ bs,
                      const float* __restrict__ Wt, const float* __restrict__ bt,
                      const float* __restrict__ be) {
    extern __shared__ uint32_t sm1[];
    uint32_t* sX = sm1;                  // 128 x 132
    uint32_t* sW = sm1 + 128 * 132;      // 64 x 132

    const int tid = threadIdx.x;
    const int warp = tid >> 5, lane = tid & 31, g = lane >> 2, tig = lane & 3;
    const int m0 = blockIdx.x * 128;

    // load X tile (zero-fill OOB rows), convert to tf32
#pragma unroll
    for (int i = 0; i < 16; i++) {
        int idx = i * 256 + tid;          // 4096 float4
        int r = idx >> 5, c4 = (idx & 31) * 4;
        float4 v = make_float4(0.f, 0.f, 0.f, 0.f);
        if (m0 + r < NN) v = *(const float4*)(x + (size_t)(m0 + r) * 128 + c4);
        uint32_t* d = sX + r * 132 + c4;
        d[0] = f2tf(v.x); d[1] = f2tf(v.y); d[2] = f2tf(v.z); d[3] = f2tf(v.w);
    }

    const int lr0 = warp * 16 + g;
    const uint32_t* A0 = sX + lr0 * 132;
    const uint32_t* A1 = A0 + 8 * 132;
    const int gr0 = m0 + lr0;

    for (int table = 0; table < 2; table++) {
        const float* W = table ? Wt : Ws;
        __syncthreads();  // protect sW from previous iteration's readers
#pragma unroll
        for (int i = 0; i < 8; i++) {
            int idx = i * 256 + tid;      // 2048 float4
            int r = idx >> 5, c4 = (idx & 31) * 4;
            float4 v = *(const float4*)(W + r * 128 + c4);
            uint32_t* d = sW + r * 132 + c4;
            d[0] = f2tf(v.x); d[1] = f2tf(v.y); d[2] = f2tf(v.z); d[3] = f2tf(v.w);
        }
        __syncthreads();

        float C[8][4];
#pragma unroll
        for (int nt = 0; nt < 8; nt++) { C[nt][0] = C[nt][1] = C[nt][2] = C[nt][3] = 0.f; }

#pragma unroll
        for (int kt = 0; kt < 16; kt++) {
            uint32_t a0 = A0[kt * 8 + tig], a1 = A1[kt * 8 + tig];
            uint32_t a2 = A0[kt * 8 + tig + 4], a3 = A1[kt * 8 + tig + 4];
#pragma unroll
            for (int nt = 0; nt < 8; nt++) {
                const uint32_t* br = sW + (nt * 8 + g) * 132 + kt * 8;
                mma8(C[nt], a0, a1, a2, a3, br[tig], br[tig + 4]);
            }
        }

        float* dst = table ? g_xt : g_xs;
#pragma unroll
        for (int nt = 0; nt < 8; nt++) {
            int c = nt * 8 + 2 * tig;
            float bias0, bias1;
            if (table == 0) { bias0 = bs[c] + be[c]; bias1 = bs[c + 1] + be[c + 1]; }
            else            { bias0 = bt[c];         bias1 = bt[c + 1]; }
            if (gr0 < NN) {
                float2 v = make_float2(C[nt][0] + bias0, C[nt][1] + bias1);
                *(float2*)(dst + (size_t)gr0 * 64 + c) = v;
            }
            if (gr0 + 8 < NN) {
                float2 v = make_float2(C[nt][2] + bias0, C[nt][3] + bias1);
                *(float2*)(dst + (size_t)(gr0 + 8) * 64 + c) = v;
            }
        }
    }
}

// ---------------------------------------------------------------------------
// Kernel 2: fused edge MLP
// out = gelu(EA@We^T + gather(xs,src) + gather(xt,tgt)) @ W1^T + b1
// 128 edges per block, 256 threads (8 warps x 16 rows)
// edge_index is INT32 (JAX default config downcasts int64 -> int32)
// ---------------------------------------------------------------------------
__global__ __launch_bounds__(256)
void edge_mlp_kernel(const float* __restrict__ ea,
                     const int* __restrict__ eidx,
                     const float* __restrict__ We,
                     const float* __restrict__ W1,
                     const float* __restrict__ b1,
                     float* __restrict__ out) {
    extern __shared__ uint32_t sm2[];
    uint32_t* sEA = sm2;                   // 128 x 68 (tf32; reused for H)
    uint32_t* sWe = sm2 + 128 * 68;        // 64 x 68
    uint32_t* sW1 = sWe + 64 * 68;         // 64 x 68
    int* sSrc = (int*)(sW1 + 64 * 68);     // 128
    int* sTgt = sSrc + 128;                // 128
    float* sB1 = (float*)(sTgt + 128);     // 64

    const int tid = threadIdx.x;
    const int warp = tid >> 5, lane = tid & 31, g = lane >> 2, tig = lane & 3;
    const long long e0 = (long long)blockIdx.x * 128;

    // EA tile (zero-fill OOB rows)
#pragma unroll
    for (int i = 0; i < 8; i++) {
        int idx = i * 256 + tid;           // 2048 float4
        int r = idx >> 4, c4 = (idx & 15) * 4;
        float4 v = make_float4(0.f, 0.f, 0.f, 0.f);
        if (e0 + r < NE) v = *(const float4*)(ea + (size_t)(e0 + r) * 64 + c4);
        uint32_t* d = sEA + r * 68 + c4;
        d[0] = f2tf(v.x); d[1] = f2tf(v.y); d[2] = f2tf(v.z); d[3] = f2tf(v.w);
    }
    // weights -> tf32 smem
#pragma unroll
    for (int i = 0; i < 4; i++) {
        int idx = i * 256 + tid;           // 1024 float4
        int r = idx >> 4, c4 = (idx & 15) * 4;
        float4 v = *(const float4*)(We + r * 64 + c4);
        uint32_t* d = sWe + r * 68 + c4;
        d[0] = f2tf(v.x); d[1] = f2tf(v.y); d[2] = f2tf(v.z); d[3] = f2tf(v.w);
        float4 w = *(const float4*)(W1 + r * 64 + c4);
        uint32_t* d2 = sW1 + r * 68 + c4;
        d2[0] = f2tf(w.x); d2[1] = f2tf(w.y); d2[2] = f2tf(w.z); d2[3] = f2tf(w.w);
    }
    // edge indices: int32, row 0 = src at eidx[e], row 1 = tgt at eidx[NE + e].
    // Clamp defensively to [0, NN) so a bad index degrades to wrong-answer, not IMA.
    if (tid < 128) {
        long long e = e0 + tid;
        int v = (e < NE) ? eidx[e] : 0;
        sSrc[tid] = min(max(v, 0), NN - 1);
    } else {
        long long e = e0 + (tid - 128);
        int v = (e < NE) ? eidx[NE + e] : 0;
        sTgt[tid - 128] = min(max(v, 0), NN - 1);
    }
    if (tid < 64) sB1[tid] = b1[tid];
    __syncthreads();

    const int lr0 = warp * 16 + g, lr1 = lr0 + 8;
    uint32_t* A0 = sEA + lr0 * 68;
    uint32_t* A1 = sEA + lr1 * 68;

    // ---- stage 1: H = EA @ We^T ----
    float C[8][4];
#pragma unroll
    for (int nt = 0; nt < 8; nt++) { C[nt][0] = C[nt][1] = C[nt][2] = C[nt][3] = 0.f; }
#pragma unroll
    for (int kt = 0; kt < 8; kt++) {
        uint32_t a0 = A0[kt * 8 + tig], a1 = A1[kt * 8 + tig];
        uint32_t a2 = A0[kt * 8 + tig + 4], a3 = A1[kt * 8 + tig + 4];
#pragma unroll
        for (int nt = 0; nt < 8; nt++) {
            const uint32_t* br = sWe + (nt * 8 + g) * 68 + kt * 8;
            mma8(C[nt], a0, a1, a2, a3, br[tig], br[tig + 4]);
        }
    }

    // ---- gather (L2-resident), GELU, write H back into own smem rows ----
    const float* xs0 = g_xs + (size_t)sSrc[lr0] * 64;
    const float* xt0 = g_xt + (size_t)sTgt[lr0] * 64;
    const float* xs1 = g_xs + (size_t)sSrc[lr1] * 64;
    const float* xt1 = g_xt + (size_t)sTgt[lr1] * 64;
#pragma unroll
    for (int nt = 0; nt < 8; nt++) {
        int c = nt * 8 + 2 * tig;
        float2 p0 = *(const float2*)(xs0 + c);
        float2 q0 = *(const float2*)(xt0 + c);
        float2 p1 = *(const float2*)(xs1 + c);
        float2 q1 = *(const float2*)(xt1 + c);
        float h0 = gelu_tanh(C[nt][0] + p0.x + q0.x);
        float h1 = gelu_tanh(C[nt][1] + p0.y + q0.y);
        float h2 = gelu_tanh(C[nt][2] + p1.x + q1.x);
        float h3 = gelu_tanh(C[nt][3] + p1.y + q1.y);
        A0[c] = f2tf(h0); A0[c + 1] = f2tf(h1);
        A1[c] = f2tf(h2); A1[c + 1] = f2tf(h3);
    }
    __syncwarp();  // rows are warp-private: warp-level visibility is enough

    // ---- stage 2: OUT = H @ W1^T ----
#pragma unroll
    for (int nt = 0; nt < 8; nt++) { C[nt][0] = C[nt][1] = C[nt][2] = C[nt][3] = 0.f; }
#pragma unroll
    for (int kt = 0; kt < 8; kt++) {
        uint32_t a0 = A0[kt * 8 + tig], a1 = A1[kt * 8 + tig];
        uint32_t a2 = A0[kt * 8 + tig + 4], a3 = A1[kt * 8 + tig + 4];
#pragma unroll
        for (int nt = 0; nt < 8; nt++) {
            const uint32_t* br = sW1 + (nt * 8 + g) * 68 + kt * 8;
            mma8(C[nt], a0, a1, a2, a3, br[tig], br[tig + 4]);
        }
    }

    const long long ge0 = e0 + lr0;
#pragma unroll
    for (int nt = 0; nt < 8; nt++) {
        int c = nt * 8 + 2 * tig;
        if (ge0 < NE) {
            float2 v = make_float2(C[nt][0] + sB1[c], C[nt][1] + sB1[c + 1]);
            *(float2*)(out + (size_t)ge0 * 64 + c) = v;
        }
        if (ge0 + 8 < NE) {
            float2 v = make_float2(C[nt][2] + sB1[c], C[nt][3] + sB1[c + 1]);
            *(float2*)(out + ((size_t)ge0 + 8) * 64 + c) = v;
        }
    }
}

extern "C" void kernel_launch(void* const* d_in, const int* in_sizes, int n_in,
                              void* d_out, int out_size) {
    const float* x   = (const float*)d_in[0];
    const int*   ei  = (const int*)d_in[1];     // int32 (JAX default x64-disabled)
    const float* ea  = (const float*)d_in[2];
    const float* We  = (const float*)d_in[3];
    const float* be  = (const float*)d_in[4];
    const float* Ws  = (const float*)d_in[5];
    const float* bs  = (const float*)d_in[6];
    const float* Wt  = (const float*)d_in[7];
    const float* bt  = (const float*)d_in[8];
    const float* W1  = (const float*)d_in[9];
    const float* b1  = (const float*)d_in[10];
    float* out = (float*)d_out;

    const size_t smem1 = (size_t)(128 * 132 + 64 * 132) * 4;            // ~99 KB
    const size_t smem2 = (size_t)(128 * 68 + 2 * 64 * 68 + 320) * 4;    // ~69 KB
    cudaFuncSetAttribute(node_proj_kernel, cudaFuncAttributeMaxDynamicSharedMemorySize, (int)smem1);
    cudaFuncSetAttribute(edge_mlp_kernel,  cudaFuncAttributeMaxDynamicSharedMemorySize, (int)smem2);

    node_proj_kernel<<<(NN + 127) / 128, 256, smem1>>>(x, Ws, bs, Wt, bt, be);
    edge_mlp_kernel<<<(NE + 127) / 128, 256, smem2>>>(ea, ei, We, W1, b1, out);
}

// round 3
// speedup vs baseline: 1.1591x; 1.1591x over previous
#include <cuda_runtime.h>
#include <cstdint>
#include <cstddef>

#define NE 1000000
#define NN 50000

// scratch for node projections (static device globals: allowed, no runtime alloc)
__device__ float g_xs[(size_t)NN * 64];
__device__ float g_xt[(size_t)NN * 64];

__device__ __forceinline__ uint32_t f2tf(float f) {
    uint32_t r;
    asm("cvt.rna.tf32.f32 %0, %1;" : "=r"(r) : "f"(f));
    return r;
}

__device__ __forceinline__ void mma8(float c[4],
                                     uint32_t a0, uint32_t a1, uint32_t a2, uint32_t a3,
                                     uint32_t b0, uint32_t b1) {
    asm volatile(
        "mma.sync.aligned.m16n8k8.row.col.f32.tf32.tf32.f32 "
        "{%0,%1,%2,%3}, {%4,%5,%6,%7}, {%8,%9}, {%10,%11,%12,%13};\n"
        : "=f"(c[0]), "=f"(c[1]), "=f"(c[2]), "=f"(c[3])
        : "r"(a0), "r"(a1), "r"(a2), "r"(a3), "r"(b0), "r"(b1),
          "f"(c[0]), "f"(c[1]), "f"(c[2]), "f"(c[3]));
}

// jax.nn.gelu approximate: gelu(v) = v * sigmoid(2u), u = sqrt(2/pi)(v + 0.044715 v^3)
__device__ __forceinline__ float gelu_tanh(float v) {
    float v3 = v * v * v;
    float m2u = -1.5957691216057308f * v - 0.07135481627260025f * v3;  // -2u
    float e = __expf(m2u);
    return __fdividef(v, 1.0f + e);
}

// ---------------------------------------------------------------------------
// Kernel 1: node projections  XS = X@Ws^T + (bs+be),  XT = X@Wt^T + bt
// ---------------------------------------------------------------------------
__global__ __launch_bounds__(256)
void node_proj_kernel(const float* __restrict__ x,
                      const float* __restrict__ Ws, const float* __restrict__ bs,
                      const float* __restrict__ Wt, const float* __restrict__ bt,
                      const float* __restrict__ be) {
    extern __shared__ uint32_t sm1[];
    uint32_t* sX = sm1;                  // 128 x 132
    uint32_t* sW = sm1 + 128 * 132;      // 64 x 132

    const int tid = threadIdx.x;
    const int warp = tid >> 5, lane = tid & 31, g = lane >> 2, tig = lane & 3;
    const int m0 = blockIdx.x * 128;

#pragma unroll
    for (int i = 0; i < 16; i++) {
        int idx = i * 256 + tid;          // 4096 float4
        int r = idx >> 5, c4 = (idx & 31) * 4;
        float4 v = make_float4(0.f, 0.f, 0.f, 0.f);
        if (m0 + r < NN) v = *(const float4*)(x + (size_t)(m0 + r) * 128 + c4);
        uint32_t* d = sX + r * 132 + c4;
        d[0] = f2tf(v.x); d[1] = f2tf(v.y); d[2] = f2tf(v.z); d[3] = f2tf(v.w);
    }

    const int lr0 = warp * 16 + g;
    const uint32_t* A0 = sX + lr0 * 132;
    const uint32_t* A1 = A0 + 8 * 132;
    const int gr0 = m0 + lr0;

    for (int table = 0; table < 2; table++) {
        const float* W = table ? Wt : Ws;
        __syncthreads();
#pragma unroll
        for (int i = 0; i < 8; i++) {
            int idx = i * 256 + tid;      // 2048 float4
            int r = idx >> 5, c4 = (idx & 31) * 4;
            float4 v = *(const float4*)(W + r * 128 + c4);
            uint32_t* d = sW + r * 132 + c4;
            d[0] = f2tf(v.x); d[1] = f2tf(v.y); d[2] = f2tf(v.z); d[3] = f2tf(v.w);
        }
        __syncthreads();

        float C[8][4];
#pragma unroll
        for (int nt = 0; nt < 8; nt++) { C[nt][0] = C[nt][1] = C[nt][2] = C[nt][3] = 0.f; }

#pragma unroll
        for (int kt = 0; kt < 16; kt++) {
            uint32_t a0 = A0[kt * 8 + tig], a1 = A1[kt * 8 + tig];
            uint32_t a2 = A0[kt * 8 + tig + 4], a3 = A1[kt * 8 + tig + 4];
#pragma unroll
            for (int nt = 0; nt < 8; nt++) {
                const uint32_t* br = sW + (nt * 8 + g) * 132 + kt * 8;
                mma8(C[nt], a0, a1, a2, a3, br[tig], br[tig + 4]);
            }
        }

        float* dst = table ? g_xt : g_xs;
#pragma unroll
        for (int nt = 0; nt < 8; nt++) {
            int c = nt * 8 + 2 * tig;
            float bias0, bias1;
            if (table == 0) { bias0 = bs[c] + be[c]; bias1 = bs[c + 1] + be[c + 1]; }
            else            { bias0 = bt[c];         bias1 = bt[c + 1]; }
            if (gr0 < NN) {
                float2 v = make_float2(C[nt][0] + bias0, C[nt][1] + bias1);
                *(float2*)(dst + (size_t)gr0 * 64 + c) = v;
            }
            if (gr0 + 8 < NN) {
                float2 v = make_float2(C[nt][2] + bias0, C[nt][3] + bias1);
                *(float2*)(dst + (size_t)(gr0 + 8) * 64 + c) = v;
            }
        }
    }
}

// ---------------------------------------------------------------------------
// Kernel 2: fused edge MLP (v3)
// out = gelu(EA@We^T + gather(xs,src) + gather(xt,tgt)) @ W1^T + b1
// 256 edges per block, 8 warps, M=32 rows per warp (2 m-tiles).
// Weights in pair-interleaved layout (k, k+4 adjacent), stride 72 -> LDS.64
// conflict-free per half-warp. sEA plain layout stride 68 (conflict-free LDS.32,
// H write-back as STS.64 pairs).
// ---------------------------------------------------------------------------
__global__ __launch_bounds__(256, 2)
void edge_mlp_kernel(const float* __restrict__ ea,
                     const int* __restrict__ eidx,
                     const float* __restrict__ We,
                     const float* __restrict__ W1,
                     const float* __restrict__ b1,
                     float* __restrict__ out) {
    extern __shared__ uint32_t sm2[];
    uint32_t* sEA = sm2;                     // 256 x 68 (tf32; reused for H)
    uint32_t* sWe = sm2 + 256 * 68;          // 64 x 72 interleaved
    uint32_t* sW1 = sWe + 64 * 72;           // 64 x 72 interleaved
    int* sSrc = (int*)(sW1 + 64 * 72);       // 256
    int* sTgt = sSrc + 256;                  // 256
    float* sB1 = (float*)(sTgt + 256);       // 64

    const int tid = threadIdx.x;
    const int warp = tid >> 5, lane = tid & 31, g = lane >> 2, tig = lane & 3;
    const long long e0 = (long long)blockIdx.x * 256;

    // ---- stage EA tile (zero-fill OOB rows) ----
#pragma unroll
    for (int i = 0; i < 16; i++) {
        int idx = i * 256 + tid;             // 4096 float4
        int r = idx >> 4, c4 = (idx & 15) * 4;
        float4 v = make_float4(0.f, 0.f, 0.f, 0.f);
        if (e0 + r < NE) v = *(const float4*)(ea + (size_t)(e0 + r) * 64 + c4);
        uint32_t* d = sEA + r * 68 + c4;
        d[0] = f2tf(v.x); d[1] = f2tf(v.y); d[2] = f2tf(v.z); d[3] = f2tf(v.w);
    }
    // ---- weights -> interleaved tf32 smem: pos(k) = (k>>3)*8 + ((k&3)*2 | ((k>>2)&1)) ----
#pragma unroll
    for (int i = 0; i < 8; i++) {
        int idx = i * 256 + tid;             // 2048 float4 tasks over both tables
        int table = idx >> 10;
        int rem = idx & 1023;
        int r = rem >> 4, c4 = (rem & 15) * 4;
        const float* W = table ? W1 : We;
        uint32_t* dst = table ? sW1 : sWe;
        float4 v = *(const float4*)(W + r * 64 + c4);
        float vv[4] = {v.x, v.y, v.z, v.w};
#pragma unroll
        for (int m = 0; m < 4; m++) {
            int c = c4 + m;
            int pos = ((c >> 3) << 3) + (((c & 3) << 1) | ((c >> 2) & 1));
            dst[r * 72 + pos] = f2tf(vv[m]);
        }
    }
    // ---- edge indices (int32; clamp defensively) ----
#pragma unroll
    for (int j = 0; j < 1; j++) { }
    {
        long long e = e0 + tid;
        int vs = (e < NE) ? eidx[e] : 0;
        int vt = (e < NE) ? eidx[NE + e] : 0;
        sSrc[tid] = min(max(vs, 0), NN - 1);
        sTgt[tid] = min(max(vt, 0), NN - 1);
    }
    if (tid < 64) sB1[tid] = b1[tid];
    __syncthreads();

    const int rb = warp * 32 + g;            // row slots: rb, rb+8, rb+16, rb+24
    uint32_t* A0 = sEA + rb * 68;            // mtile 0: rows rb, rb+8
    uint32_t* A1 = A0 + 8 * 68;
    uint32_t* A2 = A0 + 16 * 68;             // mtile 1: rows rb+16, rb+24
    uint32_t* A3 = A0 + 24 * 68;

    // ---- stage 1: H = EA @ We^T ----
    float C[2][8][4];
#pragma unroll
    for (int s = 0; s < 2; s++)
#pragma unroll
        for (int nt = 0; nt < 8; nt++) { C[s][nt][0] = C[s][nt][1] = C[s][nt][2] = C[s][nt][3] = 0.f; }

#pragma unroll
    for (int kt = 0; kt < 8; kt++) {
        const int ko = kt * 8;
        uint32_t a00 = A0[ko + tig], a01 = A1[ko + tig];
        uint32_t a02 = A0[ko + tig + 4], a03 = A1[ko + tig + 4];
        uint32_t a10 = A2[ko + tig], a11 = A3[ko + tig];
        uint32_t a12 = A2[ko + tig + 4], a13 = A3[ko + tig + 4];
#pragma unroll
        for (int nt = 0; nt < 8; nt++) {
            uint2 b = *(const uint2*)(sWe + (nt * 8 + g) * 72 + ko + 2 * tig);
            mma8(C[0][nt], a00, a01, a02, a03, b.x, b.y);
            mma8(C[1][nt], a10, a11, a12, a13, b.x, b.y);
        }
    }

    // ---- gather (L2-resident) + GELU, write H back into own smem rows (STS.64) ----
#pragma unroll
    for (int s = 0; s < 4; s++) {
        const int row = rb + 8 * s;
        const float* xs = g_xs + (size_t)sSrc[row] * 64;
        const float* xt = g_xt + (size_t)sTgt[row] * 64;
        float* Cr;  // C[s>>1][nt][(s&1)*2 + {0,1}]
#pragma unroll
        for (int nt = 0; nt < 8; nt++) {
            int c = nt * 8 + 2 * tig;
            float2 p = *(const float2*)(xs + c);
            float2 q = *(const float2*)(xt + c);
            float v0 = C[s >> 1][nt][(s & 1) * 2 + 0] + p.x + q.x;
            float v1 = C[s >> 1][nt][(s & 1) * 2 + 1] + p.y + q.y;
            uint2 h;
            h.x = f2tf(gelu_tanh(v0));
            h.y = f2tf(gelu_tanh(v1));
            *(uint2*)(sEA + row * 68 + c) = h;
        }
        (void)Cr;
    }
    __syncwarp();  // rows are warp-private

    // ---- stage 2: OUT = H @ W1^T ----
#pragma unroll
    for (int s = 0; s < 2; s++)
#pragma unroll
        for (int nt = 0; nt < 8; nt++) { C[s][nt][0] = C[s][nt][1] = C[s][nt][2] = C[s][nt][3] = 0.f; }

#pragma unroll
    for (int kt = 0; kt < 8; kt++) {
        const int ko = kt * 8;
        uint32_t a00 = A0[ko + tig], a01 = A1[ko + tig];
        uint32_t a02 = A0[ko + tig + 4], a03 = A1[ko + tig + 4];
        uint32_t a10 = A2[ko + tig], a11 = A3[ko + tig];
        uint32_t a12 = A2[ko + tig + 4], a13 = A3[ko + tig + 4];
#pragma unroll
        for (int nt = 0; nt < 8; nt++) {
            uint2 b = *(const uint2*)(sW1 + (nt * 8 + g) * 72 + ko + 2 * tig);
            mma8(C[0][nt], a00, a01, a02, a03, b.x, b.y);
            mma8(C[1][nt], a10, a11, a12, a13, b.x, b.y);
        }
    }

    // ---- epilogue: +b1, store ----
#pragma unroll
    for (int s = 0; s < 4; s++) {
        const long long ge = e0 + rb + 8 * s;
        if (ge < NE) {
            float* orow = out + (size_t)ge * 64;
#pragma unroll
            for (int nt = 0; nt < 8; nt++) {
                int c = nt * 8 + 2 * tig;
                float2 v = make_float2(C[s >> 1][nt][(s & 1) * 2 + 0] + sB1[c],
                                       C[s >> 1][nt][(s & 1) * 2 + 1] + sB1[c + 1]);
                *(float2*)(orow + c) = v;
            }
        }
    }
}

extern "C" void kernel_launch(void* const* d_in, const int* in_sizes, int n_in,
                              void* d_out, int out_size) {
    const float* x   = (const float*)d_in[0];
    const int*   ei  = (const int*)d_in[1];     // int32 (JAX default x64-disabled)
    const float* ea  = (const float*)d_in[2];
    const float* We  = (const float*)d_in[3];
    const float* be  = (const float*)d_in[4];
    const float* Ws  = (const float*)d_in[5];
    const float* bs  = (const float*)d_in[6];
    const float* Wt  = (const float*)d_in[7];
    const float* bt  = (const float*)d_in[8];
    const float* W1  = (const float*)d_in[9];
    const float* b1  = (const float*)d_in[10];
    float* out = (float*)d_out;

    const size_t smem1 = (size_t)(128 * 132 + 64 * 132) * 4;                  // ~99 KB
    const size_t smem2 = (size_t)(256 * 68 + 2 * 64 * 72 + 512 + 64 + 16) * 4; // ~109 KB
    cudaFuncSetAttribute(node_proj_kernel, cudaFuncAttributeMaxDynamicSharedMemorySize, (int)smem1);
    cudaFuncSetAttribute(edge_mlp_kernel,  cudaFuncAttributeMaxDynamicSharedMemorySize, (int)smem2);

    node_proj_kernel<<<(NN + 127) / 128, 256, smem1>>>(x, Ws, bs, Wt, bt, be);
    edge_mlp_kernel<<<(NE + 255) / 256, 256, smem2>>>(ea, ei, We, W1, b1, out);
}

// round 6
// speedup vs baseline: 1.3037x; 1.1247x over previous
#include <cuda_runtime.h>
#include <cstdint>
#include <cstddef>

#define NE 1000000
#define NN 50000
#define NT ((NE + 255) / 256)
#define PGRID 296

// node projections stored COLUMN-PERMUTED: value of logical feature c lives at
// pos(c) = (nt>>1)*16 + tig*4 + (nt&1)*2 + b   where c = 8*nt + 2*tig + b.
// This makes each mma-fragment owner's 16 features 4 contiguous float4s.
__device__ float g_xs[(size_t)NN * 64];
__device__ float g_xt[(size_t)NN * 64];

__device__ __forceinline__ uint32_t f2tf(float f) {
    uint32_t r;
    asm("cvt.rna.tf32.f32 %0, %1;" : "=r"(r) : "f"(f));
    return r;
}

__device__ __forceinline__ void mma8(float c[4],
                                     uint32_t a0, uint32_t a1, uint32_t a2, uint32_t a3,
                                     uint32_t b0, uint32_t b1) {
    asm volatile(
        "mma.sync.aligned.m16n8k8.row.col.f32.tf32.tf32.f32 "
        "{%0,%1,%2,%3}, {%4,%5,%6,%7}, {%8,%9}, {%10,%11,%12,%13};\n"
        : "=f"(c[0]), "=f"(c[1]), "=f"(c[2]), "=f"(c[3])
        : "r"(a0), "r"(a1), "r"(a2), "r"(a3), "r"(b0), "r"(b1),
          "f"(c[0]), "f"(c[1]), "f"(c[2]), "f"(c[3]));
}

// jax.nn.gelu approximate: gelu(v) = v * sigmoid(2u), u = sqrt(2/pi)(v+0.044715v^3)
__device__ __forceinline__ float gelu_tanh(float v) {
    float v3 = v * v * v;
    float m2u = -1.5957691216057308f * v - 0.07135481627260025f * v3;  // -2u
    float e = __expf(m2u);
    return __fdividef(v, 1.0f + e);
}

// ---------------------------------------------------------------------------
// Kernel 1: node projections  XS = X@Ws^T + (bs+be),  XT = X@Wt^T + bt
// (output written in pos(c)-permuted column order)
// ---------------------------------------------------------------------------
__global__ __launch_bounds__(256)
void node_proj_kernel(const float* __restrict__ x,
                      const float* __restrict__ Ws, const float* __restrict__ bs,
                      const float* __restrict__ Wt, const float* __restrict__ bt,
                      const float* __restrict__ be) {
    extern __shared__ uint32_t sm1[];
    uint32_t* sX = sm1;                  // 128 x 132
    uint32_t* sW = sm1 + 128 * 132;      // 64 x 132

    const int tid = threadIdx.x;
    const int warp = tid >> 5, lane = tid & 31, g = lane >> 2, tig = lane & 3;
    const int m0 = blockIdx.x * 128;

#pragma unroll
    for (int i = 0; i < 16; i++) {
        int idx = i * 256 + tid;
        int r = idx >> 5, c4 = (idx & 31) * 4;
        float4 v = make_float4(0.f, 0.f, 0.f, 0.f);
        if (m0 + r < NN) v = *(const float4*)(x + (size_t)(m0 + r) * 128 + c4);
        uint32_t* d = sX + r * 132 + c4;
        d[0] = f2tf(v.x); d[1] = f2tf(v.y); d[2] = f2tf(v.z); d[3] = f2tf(v.w);
    }

    const int lr0 = warp * 16 + g;
    const uint32_t* A0 = sX + lr0 * 132;
    const uint32_t* A1 = A0 + 8 * 132;
    const int gr0 = m0 + lr0;

    for (int table = 0; table < 2; table++) {
        const float* W = table ? Wt : Ws;
        __syncthreads();
#pragma unroll
        for (int i = 0; i < 8; i++) {
            int idx = i * 256 + tid;
            int r = idx >> 5, c4 = (idx & 31) * 4;
            float4 v = *(const float4*)(W + r * 128 + c4);
            uint32_t* d = sW + r * 132 + c4;
            d[0] = f2tf(v.x); d[1] = f2tf(v.y); d[2] = f2tf(v.z); d[3] = f2tf(v.w);
        }
        __syncthreads();

        float C[8][4];
#pragma unroll
        for (int nt = 0; nt < 8; nt++) { C[nt][0] = C[nt][1] = C[nt][2] = C[nt][3] = 0.f; }

#pragma unroll
        for (int kt = 0; kt < 16; kt++) {
            uint32_t a0 = A0[kt * 8 + tig], a1 = A1[kt * 8 + tig];
            uint32_t a2 = A0[kt * 8 + tig + 4], a3 = A1[kt * 8 + tig + 4];
#pragma unroll
            for (int nt = 0; nt < 8; nt++) {
                const uint32_t* br = sW + (nt * 8 + g) * 132 + kt * 8;
                mma8(C[nt], a0, a1, a2, a3, br[tig], br[tig + 4]);
            }
        }

        float* dst = table ? g_xt : g_xs;
#pragma unroll
        for (int nt = 0; nt < 8; nt++) {
            int c = nt * 8 + 2 * tig;                                  // logical col
            int pos = (nt >> 1) * 16 + tig * 4 + (nt & 1) * 2;         // permuted slot
            float bias0, bias1;
            if (table == 0) { bias0 = bs[c] + be[c]; bias1 = bs[c + 1] + be[c + 1]; }
            else            { bias0 = bt[c];         bias1 = bt[c + 1]; }
            if (gr0 < NN) {
                float2 v = make_float2(C[nt][0] + bias0, C[nt][1] + bias1);
                *(float2*)(dst + (size_t)gr0 * 64 + pos) = v;
            }
            if (gr0 + 8 < NN) {
                float2 v = make_float2(C[nt][2] + bias0, C[nt][3] + bias1);
                *(float2*)(dst + (size_t)(gr0 + 8) * 64 + pos) = v;
            }
        }
    }
}

// ---------------------------------------------------------------------------
// Kernel 2: fused edge MLP, persistent CTAs (weights staged once per CTA)
// 256 edges per tile, 8 warps, M=32 rows/warp.
// W1 rows stored at permuted physical position rp = pos^{-1}(r) so output cols
// per thread are 4 consecutive logical features -> float4 gathers + STG.128.
// ---------------------------------------------------------------------------
__global__ __launch_bounds__(256, 2)
void edge_mlp_kernel(const float* __restrict__ ea,
                     const int* __restrict__ eidx,
                     const float* __restrict__ We,
                     const float* __restrict__ W1,
                     const float* __restrict__ b1,
                     float* __restrict__ out) {
    extern __shared__ uint32_t sm2[];
    uint32_t* sEA = sm2;                     // 256 x 68 (tf32; reused for H)
    uint32_t* sWe = sm2 + 256 * 68;          // 64 x 72 col-interleaved
    uint32_t* sW1 = sWe + 64 * 72;           // 64 x 72 col-interleaved + row-permuted
    int* sSrc = (int*)(sW1 + 64 * 72);       // 256
    int* sTgt = sSrc + 256;                  // 256
    float* sB1 = (float*)(sTgt + 256);       // 64

    const int tid = threadIdx.x;
    const int warp = tid >> 5, lane = tid & 31, g = lane >> 2, tig = lane & 3;

    // ---- stage weights ONCE (col pair-interleave; W1 also row-permuted) ----
#pragma unroll
    for (int i = 0; i < 8; i++) {
        int idx = i * 256 + tid;             // 2048 float4 over both tables
        int table = idx >> 10;
        int rem = idx & 1023;
        int r = rem >> 4, c4 = (rem & 15) * 4;
        const float* W = table ? W1 : We;
        uint32_t* dst = table ? sW1 : sWe;
        // W1: physical row rp = pos^{-1}(r): rp3<-r1, rp2<-r3, rp1<-r2; bits 5,4,0 fixed
        int rp = table
               ? ((r & 0x31) | ((r & 0x2) << 2) | ((r & 0x8) >> 1) | ((r & 0x4) >> 1))
               : r;
        float4 v = *(const float4*)(W + r * 64 + c4);
        float vv[4] = {v.x, v.y, v.z, v.w};
#pragma unroll
        for (int m = 0; m < 4; m++) {
            int c = c4 + m;
            int kpos = ((c >> 3) << 3) + (((c & 3) << 1) | ((c >> 2) & 1));
            dst[rp * 72 + kpos] = f2tf(vv[m]);
        }
    }
    if (tid < 64) sB1[tid] = b1[tid];
    __syncthreads();

    const int rb = warp * 32 + g;            // row slots: rb, rb+8, rb+16, rb+24
    uint32_t* A0 = sEA + rb * 68;
    uint32_t* A1 = A0 + 8 * 68;
    uint32_t* A2 = A0 + 16 * 68;
    uint32_t* A3 = A0 + 24 * 68;

    for (int tile = blockIdx.x; tile < NT; tile += gridDim.x) {
        const long long e0 = (long long)tile * 256;

        // ---- stage EA tile (zero-fill OOB rows) ----
#pragma unroll
        for (int i = 0; i < 16; i++) {
            int idx = i * 256 + tid;         // 4096 float4
            int r = idx >> 4, c4 = (idx & 15) * 4;
            float4 v = make_float4(0.f, 0.f, 0.f, 0.f);
            if (e0 + r < NE) v = *(const float4*)(ea + (size_t)(e0 + r) * 64 + c4);
            uint32_t* d = sEA + r * 68 + c4;
            d[0] = f2tf(v.x); d[1] = f2tf(v.y); d[2] = f2tf(v.z); d[3] = f2tf(v.w);
        }
        {   // edge indices (int32; clamp defensively)
            long long e = e0 + tid;
            int vs = (e < NE) ? eidx[e] : 0;
            int vt = (e < NE) ? eidx[NE + e] : 0;
            sSrc[tid] = min(max(vs, 0), NN - 1);
            sTgt[tid] = min(max(vt, 0), NN - 1);
        }
        __syncthreads();

        // ---- stage 1: H = EA @ We^T ----
        float C[2][8][4];
#pragma unroll
        for (int s = 0; s < 2; s++)
#pragma unroll
            for (int nt = 0; nt < 8; nt++) { C[s][nt][0] = C[s][nt][1] = C[s][nt][2] = C[s][nt][3] = 0.f; }

#pragma unroll
        for (int kt = 0; kt < 8; kt++) {
            const int ko = kt * 8;
            uint32_t a00 = A0[ko + tig], a01 = A1[ko + tig];
            uint32_t a02 = A0[ko + tig + 4], a03 = A1[ko + tig + 4];
            uint32_t a10 = A2[ko + tig], a11 = A3[ko + tig];
            uint32_t a12 = A2[ko + tig + 4], a13 = A3[ko + tig + 4];
#pragma unroll
            for (int nt = 0; nt < 8; nt++) {
                uint2 b = *(const uint2*)(sWe + (nt * 8 + g) * 72 + ko + 2 * tig);
                mma8(C[0][nt], a00, a01, a02, a03, b.x, b.y);
                mma8(C[1][nt], a10, a11, a12, a13, b.x, b.y);
            }
        }

        // ---- gather (permuted tables, float4) + GELU -> H back into smem ----
#pragma unroll
        for (int s = 0; s < 4; s++) {
            const int row = rb + 8 * s;
            const int h = s >> 1, pb = (s & 1) * 2;
            const float* xs = g_xs + (size_t)sSrc[row] * 64 + tig * 4;
            const float* xt = g_xt + (size_t)sTgt[row] * 64 + tig * 4;
#pragma unroll
            for (int i = 0; i < 4; i++) {
                float4 p = *(const float4*)(xs + i * 16);
                float4 q = *(const float4*)(xt + i * 16);
                float v0 = C[h][2 * i + 0][pb + 0] + p.x + q.x;
                float v1 = C[h][2 * i + 0][pb + 1] + p.y + q.y;
                float v2 = C[h][2 * i + 1][pb + 0] + p.z + q.z;
                float v3 = C[h][2 * i + 1][pb + 1] + p.w + q.w;
                uint2 h0, h1;
                h0.x = f2tf(gelu_tanh(v0)); h0.y = f2tf(gelu_tanh(v1));
                h1.x = f2tf(gelu_tanh(v2)); h1.y = f2tf(gelu_tanh(v3));
                *(uint2*)(sEA + row * 68 + 16 * i + 2 * tig) = h0;       // col 8*(2i)
                *(uint2*)(sEA + row * 68 + 16 * i + 8 + 2 * tig) = h1;   // col 8*(2i+1)
            }
        }
        __syncwarp();  // H rows are warp-private

        // ---- stage 2: OUT = H @ W1p^T (N permuted) ----
#pragma unroll
        for (int s = 0; s < 2; s++)
#pragma unroll
            for (int nt = 0; nt < 8; nt++) { C[s][nt][0] = C[s][nt][1] = C[s][nt][2] = C[s][nt][3] = 0.f; }

#pragma unroll
        for (int kt = 0; kt < 8; kt++) {
            const int ko = kt * 8;
            uint32_t a00 = A0[ko + tig], a01 = A1[ko + tig];
            uint32_t a02 = A0[ko + tig + 4], a03 = A1[ko + tig + 4];
            uint32_t a10 = A2[ko + tig], a11 = A3[ko + tig];
            uint32_t a12 = A2[ko + tig + 4], a13 = A3[ko + tig + 4];
#pragma unroll
            for (int nt = 0; nt < 8; nt++) {
                uint2 b = *(const uint2*)(sW1 + (nt * 8 + g) * 72 + ko + 2 * tig);
                mma8(C[0][nt], a00, a01, a02, a03, b.x, b.y);
                mma8(C[1][nt], a10, a11, a12, a13, b.x, b.y);
            }
        }

        // ---- epilogue: +b1, STG.128 at logical cols i*16 + tig*4 ----
#pragma unroll
        for (int s = 0; s < 4; s++) {
            const long long ge = e0 + rb + 8 * s;
            const int h = s >> 1, pb = (s & 1) * 2;
            if (ge < NE) {
                float* orow = out + (size_t)ge * 64 + tig * 4;
#pragma unroll
                for (int i = 0; i < 4; i++) {
                    float4 b = *(const float4*)(sB1 + i * 16 + tig * 4);
                    float4 v;
                    v.x = C[h][2 * i + 0][pb + 0] + b.x;
                    v.y = C[h][2 * i + 0][pb + 1] + b.y;
                    v.z = C[h][2 * i + 1][pb + 0] + b.z;
                    v.w = C[h][2 * i + 1][pb + 1] + b.w;
                    *(float4*)(orow + i * 16) = v;
                }
            }
        }
        __syncthreads();  // protect sEA before next tile's staging
    }
}

extern "C" void kernel_launch(void* const* d_in, const int* in_sizes, int n_in,
                              void* d_out, int out_size) {
    const float* x   = (const float*)d_in[0];
    const int*   ei  = (const int*)d_in[1];     // int32 (JAX default x64-disabled)
    const float* ea  = (const float*)d_in[2];
    const float* We  = (const float*)d_in[3];
    const float* be  = (const float*)d_in[4];
    const float* Ws  = (const float*)d_in[5];
    const float* bs  = (const float*)d_in[6];
    const float* Wt  = (const float*)d_in[7];
    const float* bt  = (const float*)d_in[8];
    const float* W1  = (const float*)d_in[9];
    const float* b1  = (const float*)d_in[10];
    float* out = (float*)d_out;

    const size_t smem1 = (size_t)(128 * 132 + 64 * 132) * 4;                   // ~99 KB
    const size_t smem2 = (size_t)(256 * 68 + 2 * 64 * 72 + 512 + 64 + 16) * 4; // ~109 KB
    cudaFuncSetAttribute(node_proj_kernel, cudaFuncAttributeMaxDynamicSharedMemorySize, (int)smem1);
    cudaFuncSetAttribute(edge_mlp_kernel,  cudaFuncAttributeMaxDynamicSharedMemorySize, (int)smem2);

    node_proj_kernel<<<(NN + 127) / 128, 256, smem1>>>(x, Ws, bs, Wt, bt, be);
    edge_mlp_kernel<<<PGRID, 256, smem2>>>(ea, ei, We, W1, b1, out);
}

// round 7
// speedup vs baseline: 1.5200x; 1.1659x over previous
#include <cuda_runtime.h>
#include <cstdint>
#include <cstddef>

#define NE 1000000
#define NN 50000
#define NTG 31250                      // 32-edge groups (NE divisible by 32)
#define PGRID 296
#define WS (PGRID * 8)                 // total warps = tile stride

// node projections stored COLUMN-PERMUTED: logical feature c lives at
// pos(c) = (nt>>1)*16 + tig*4 + (nt&1)*2 + b   where c = 8*nt + 2*tig + b.
__device__ float g_xs[(size_t)NN * 64];
__device__ float g_xt[(size_t)NN * 64];

__device__ __forceinline__ uint32_t f2tf(float f) {
    uint32_t r;
    asm("cvt.rna.tf32.f32 %0, %1;" : "=r"(r) : "f"(f));
    return r;
}

__device__ __forceinline__ uint32_t smem_u32(const void* p) {
    uint32_t a;
    asm("{ .reg .u64 t; cvta.to.shared.u64 t, %1; cvt.u32.u64 %0, t; }" : "=r"(a) : "l"(p));
    return a;
}

__device__ __forceinline__ void mma8(float c[4],
                                     uint32_t a0, uint32_t a1, uint32_t a2, uint32_t a3,
                                     uint32_t b0, uint32_t b1) {
    asm volatile(
        "mma.sync.aligned.m16n8k8.row.col.f32.tf32.tf32.f32 "
        "{%0,%1,%2,%3}, {%4,%5,%6,%7}, {%8,%9}, {%10,%11,%12,%13};\n"
        : "=f"(c[0]), "=f"(c[1]), "=f"(c[2]), "=f"(c[3])
        : "r"(a0), "r"(a1), "r"(a2), "r"(a3), "r"(b0), "r"(b1),
          "f"(c[0]), "f"(c[1]), "f"(c[2]), "f"(c[3]));
}

// jax.nn.gelu approximate: gelu(v) = v * sigmoid(2u), u = sqrt(2/pi)(v+0.044715v^3)
__device__ __forceinline__ float gelu_tanh(float v) {
    float v3 = v * v * v;
    float m2u = -1.5957691216057308f * v - 0.07135481627260025f * v3;  // -2u
    float e = __expf(m2u);
    return __fdividef(v, 1.0f + e);
}

// ---------------------------------------------------------------------------
// Kernel 1: node projections  XS = X@Ws^T + (bs+be),  XT = X@Wt^T + bt
// (output written in pos(c)-permuted column order)
// ---------------------------------------------------------------------------
__global__ __launch_bounds__(256)
void node_proj_kernel(const float* __restrict__ x,
                      const float* __restrict__ Ws, const float* __restrict__ bs,
                      const float* __restrict__ Wt, const float* __restrict__ bt,
                      const float* __restrict__ be) {
    extern __shared__ uint32_t sm1[];
    uint32_t* sX = sm1;                  // 128 x 132
    uint32_t* sW = sm1 + 128 * 132;      // 64 x 132

    const int tid = threadIdx.x;
    const int warp = tid >> 5, lane = tid & 31, g = lane >> 2, tig = lane & 3;
    const int m0 = blockIdx.x * 128;

#pragma unroll
    for (int i = 0; i < 16; i++) {
        int idx = i * 256 + tid;
        int r = idx >> 5, c4 = (idx & 31) * 4;
        float4 v = make_float4(0.f, 0.f, 0.f, 0.f);
        if (m0 + r < NN) v = *(const float4*)(x + (size_t)(m0 + r) * 128 + c4);
        uint32_t* d = sX + r * 132 + c4;
        d[0] = f2tf(v.x); d[1] = f2tf(v.y); d[2] = f2tf(v.z); d[3] = f2tf(v.w);
    }

    const int lr0 = warp * 16 + g;
    const uint32_t* A0 = sX + lr0 * 132;
    const uint32_t* A1 = A0 + 8 * 132;
    const int gr0 = m0 + lr0;

    for (int table = 0; table < 2; table++) {
        const float* W = table ? Wt : Ws;
        __syncthreads();
#pragma unroll
        for (int i = 0; i < 8; i++) {
            int idx = i * 256 + tid;
            int r = idx >> 5, c4 = (idx & 31) * 4;
            float4 v = *(const float4*)(W + r * 128 + c4);
            uint32_t* d = sW + r * 132 + c4;
            d[0] = f2tf(v.x); d[1] = f2tf(v.y); d[2] = f2tf(v.z); d[3] = f2tf(v.w);
        }
        __syncthreads();

        float C[8][4];
#pragma unroll
        for (int nt = 0; nt < 8; nt++) { C[nt][0] = C[nt][1] = C[nt][2] = C[nt][3] = 0.f; }

#pragma unroll
        for (int kt = 0; kt < 16; kt++) {
            uint32_t a0 = A0[kt * 8 + tig], a1 = A1[kt * 8 + tig];
            uint32_t a2 = A0[kt * 8 + tig + 4], a3 = A1[kt * 8 + tig + 4];
#pragma unroll
            for (int nt = 0; nt < 8; nt++) {
                const uint32_t* br = sW + (nt * 8 + g) * 132 + kt * 8;
                mma8(C[nt], a0, a1, a2, a3, br[tig], br[tig + 4]);
            }
        }

        float* dst = table ? g_xt : g_xs;
#pragma unroll
        for (int nt = 0; nt < 8; nt++) {
            int c = nt * 8 + 2 * tig;                                  // logical col
            int pos = (nt >> 1) * 16 + tig * 4 + (nt & 1) * 2;         // permuted slot
            float bias0, bias1;
            if (table == 0) { bias0 = bs[c] + be[c]; bias1 = bs[c + 1] + be[c + 1]; }
            else            { bias0 = bt[c];         bias1 = bt[c + 1]; }
            if (gr0 < NN) {
                float2 v = make_float2(C[nt][0] + bias0, C[nt][1] + bias1);
                *(float2*)(dst + (size_t)gr0 * 64 + pos) = v;
            }
            if (gr0 + 8 < NN) {
                float2 v = make_float2(C[nt][2] + bias0, C[nt][3] + bias1);
                *(float2*)(dst + (size_t)(gr0 + 8) * 64 + pos) = v;
            }
        }
    }
}

// ---------------------------------------------------------------------------
// Kernel 2: fused edge MLP — barrier-free per-warp pipeline.
// Each warp owns 32 sEA rows + 32 indices; tiles are 32 edges per warp.
// EA staged raw f32 via cp.async (depth-1 prefetch); tf32 cvt at A-fragment
// consumption. Weights staged once per CTA (col pair-interleave; W1 row-perm).
// ---------------------------------------------------------------------------
__global__ __launch_bounds__(256, 2)
void edge_mlp_kernel(const float* __restrict__ ea,
                     const int* __restrict__ eidx,
                     const float* __restrict__ We,
                     const float* __restrict__ W1,
                     const float* __restrict__ b1,
                     float* __restrict__ out) {
    extern __shared__ uint32_t sm2[];
    uint32_t* sEA = sm2;                     // 256 x 68 (raw f32 EA, then tf32 H)
    uint32_t* sWe = sm2 + 256 * 68;          // 64 x 72 col-interleaved
    uint32_t* sW1 = sWe + 64 * 72;           // 64 x 72 col-interleaved + row-permuted
    int* sSrc = (int*)(sW1 + 64 * 72);       // 256
    int* sTgt = sSrc + 256;                  // 256
    float* sB1 = (float*)(sTgt + 256);       // 64

    const int tid = threadIdx.x;
    const int warp = tid >> 5, lane = tid & 31, g = lane >> 2, tig = lane & 3;

    // ---- stage weights ONCE (col pair-interleave; W1 also row-permuted) ----
#pragma unroll
    for (int i = 0; i < 8; i++) {
        int idx = i * 256 + tid;             // 2048 float4 over both tables
        int table = idx >> 10;
        int rem = idx & 1023;
        int r = rem >> 4, c4 = (rem & 15) * 4;
        const float* W = table ? W1 : We;
        uint32_t* dst = table ? sW1 : sWe;
        // W1: physical row rp = pos^{-1}(r): rp3<-r1, rp2<-r3, rp1<-r2; bits 5,4,0 fixed
        int rp = table
               ? ((r & 0x31) | ((r & 0x2) << 2) | ((r & 0x8) >> 1) | ((r & 0x4) >> 1))
               : r;
        float4 v = *(const float4*)(W + r * 64 + c4);
        float vv[4] = {v.x, v.y, v.z, v.w};
#pragma unroll
        for (int m = 0; m < 4; m++) {
            int c = c4 + m;
            int kpos = ((c >> 3) << 3) + (((c & 3) << 1) | ((c >> 2) & 1));
            dst[rp * 72 + kpos] = f2tf(vv[m]);
        }
    }
    if (tid < 64) sB1[tid] = b1[tid];
    __syncthreads();   // weights/bias visible; after this, warps are independent

    const int rb = warp * 32 + g;            // row slots: rb, rb+8, rb+16, rb+24
    uint32_t* A0 = sEA + rb * 68;
    uint32_t* A1 = A0 + 8 * 68;
    uint32_t* A2 = A0 + 16 * 68;
    uint32_t* A3 = A0 + 24 * 68;

    const uint32_t eaRowAddr = smem_u32(sEA) + (uint32_t)(warp * 32) * 68 * 4;
    const int wg0 = blockIdx.x * 8 + warp;   // global warp id

    // ---- prologue: prefetch EA for first tile ----
    if (wg0 < NTG) {
        const float* gsrc = ea + (size_t)wg0 * 32 * 64;
#pragma unroll
        for (int i = 0; i < 16; i++) {
            int idx = i * 32 + lane;
            int r = idx >> 4, c4 = (idx & 15) << 2;
            uint32_t dst = eaRowAddr + (uint32_t)(r * 68 + c4) * 4;
            asm volatile("cp.async.cg.shared.global [%0], [%1], 16;"
                         :: "r"(dst), "l"(gsrc + r * 64 + c4) : "memory");
        }
    }
    asm volatile("cp.async.commit_group;" ::: "memory");

    for (int tile = wg0; tile < NTG; tile += WS) {
        const long long e0 = (long long)tile * 32;

        // indices for this warp's 32 edges (int32; clamp defensively)
        {
            int vs = eidx[e0 + lane];
            int vt = eidx[NE + e0 + lane];
            sSrc[warp * 32 + lane] = min(max(vs, 0), NN - 1);
            sTgt[warp * 32 + lane] = min(max(vt, 0), NN - 1);
        }
        asm volatile("cp.async.wait_group 0;" ::: "memory");
        __syncwarp();   // EA copies + index STS visible across the warp

        // ---- stage 1: H = EA @ We^T  (A raw f32 -> tf32 at consumption) ----
        float C[2][8][4];
#pragma unroll
        for (int s = 0; s < 2; s++)
#pragma unroll
            for (int nt = 0; nt < 8; nt++) { C[s][nt][0] = C[s][nt][1] = C[s][nt][2] = C[s][nt][3] = 0.f; }

#pragma unroll
        for (int kt = 0; kt < 8; kt++) {
            const int ko = kt * 8;
            uint32_t a00 = f2tf(__uint_as_float(A0[ko + tig]));
            uint32_t a01 = f2tf(__uint_as_float(A1[ko + tig]));
            uint32_t a02 = f2tf(__uint_as_float(A0[ko + tig + 4]));
            uint32_t a03 = f2tf(__uint_as_float(A1[ko + tig + 4]));
            uint32_t a10 = f2tf(__uint_as_float(A2[ko + tig]));
            uint32_t a11 = f2tf(__uint_as_float(A3[ko + tig]));
            uint32_t a12 = f2tf(__uint_as_float(A2[ko + tig + 4]));
            uint32_t a13 = f2tf(__uint_as_float(A3[ko + tig + 4]));
#pragma unroll
            for (int nt = 0; nt < 8; nt++) {
                uint2 b = *(const uint2*)(sWe + (nt * 8 + g) * 72 + ko + 2 * tig);
                mma8(C[0][nt], a00, a01, a02, a03, b.x, b.y);
                mma8(C[1][nt], a10, a11, a12, a13, b.x, b.y);
            }
        }

        // ---- gather (permuted tables, float4) + GELU -> H back into smem ----
#pragma unroll
        for (int s = 0; s < 4; s++) {
            const int row = rb + 8 * s;
            const int h = s >> 1, pb = (s & 1) * 2;
            const float* xs = g_xs + (size_t)sSrc[row] * 64 + tig * 4;
            const float* xt = g_xt + (size_t)sTgt[row] * 64 + tig * 4;
#pragma unroll
            for (int i = 0; i < 4; i++) {
                float4 p = *(const float4*)(xs + i * 16);
                float4 q = *(const float4*)(xt + i * 16);
                float v0 = C[h][2 * i + 0][pb + 0] + p.x + q.x;
                float v1 = C[h][2 * i + 0][pb + 1] + p.y + q.y;
                float v2 = C[h][2 * i + 1][pb + 0] + p.z + q.z;
                float v3 = C[h][2 * i + 1][pb + 1] + p.w + q.w;
                uint2 h0, h1;
                h0.x = f2tf(gelu_tanh(v0)); h0.y = f2tf(gelu_tanh(v1));
                h1.x = f2tf(gelu_tanh(v2)); h1.y = f2tf(gelu_tanh(v3));
                *(uint2*)(sEA + row * 68 + 16 * i + 2 * tig) = h0;       // col 8*(2i)
                *(uint2*)(sEA + row * 68 + 16 * i + 8 + 2 * tig) = h1;   // col 8*(2i+1)
            }
        }
        __syncwarp();  // H rows are warp-private

        // ---- stage 2: OUT = H @ W1p^T (N permuted) ----
#pragma unroll
        for (int s = 0; s < 2; s++)
#pragma unroll
            for (int nt = 0; nt < 8; nt++) { C[s][nt][0] = C[s][nt][1] = C[s][nt][2] = C[s][nt][3] = 0.f; }

#pragma unroll
        for (int kt = 0; kt < 8; kt++) {
            const int ko = kt * 8;
            uint32_t a00 = A0[ko + tig], a01 = A1[ko + tig];
            uint32_t a02 = A0[ko + tig + 4], a03 = A1[ko + tig + 4];
            uint32_t a10 = A2[ko + tig], a11 = A3[ko + tig];
            uint32_t a12 = A2[ko + tig + 4], a13 = A3[ko + tig + 4];
#pragma unroll
            for (int nt = 0; nt < 8; nt++) {
                uint2 b = *(const uint2*)(sW1 + (nt * 8 + g) * 72 + ko + 2 * tig);
                mma8(C[0][nt], a00, a01, a02, a03, b.x, b.y);
                mma8(C[1][nt], a10, a11, a12, a13, b.x, b.y);
            }
        }

        // ---- prefetch next tile's EA (rows free after stage-2 A loads) ----
        if (tile + WS < NTG) {
            const float* gsrc = ea + (size_t)(tile + WS) * 32 * 64;
#pragma unroll
            for (int i = 0; i < 16; i++) {
                int idx = i * 32 + lane;
                int r = idx >> 4, c4 = (idx & 15) << 2;
                uint32_t dst = eaRowAddr + (uint32_t)(r * 68 + c4) * 4;
                asm volatile("cp.async.cg.shared.global [%0], [%1], 16;"
                             :: "r"(dst), "l"(gsrc + r * 64 + c4) : "memory");
            }
        }
        asm volatile("cp.async.commit_group;" ::: "memory");

        // ---- epilogue: +b1, STG.128 at logical cols i*16 + tig*4 ----
        float4 bia[4];
#pragma unroll
        for (int i = 0; i < 4; i++) bia[i] = *(const float4*)(sB1 + i * 16 + tig * 4);
#pragma unroll
        for (int s = 0; s < 4; s++) {
            const long long ge = e0 + rb - warp * 32 + 8 * s;  // e0 + g + 8s
            const int h = s >> 1, pb = (s & 1) * 2;
            float* orow = out + (size_t)(e0 + g + 8 * s) * 64 + tig * 4;
            (void)ge;
#pragma unroll
            for (int i = 0; i < 4; i++) {
                float4 v;
                v.x = C[h][2 * i + 0][pb + 0] + bia[i].x;
                v.y = C[h][2 * i + 0][pb + 1] + bia[i].y;
                v.z = C[h][2 * i + 1][pb + 0] + bia[i].z;
                v.w = C[h][2 * i + 1][pb + 1] + bia[i].w;
                *(float4*)(orow + i * 16) = v;
            }
        }
    }
}

extern "C" void kernel_launch(void* const* d_in, const int* in_sizes, int n_in,
                              void* d_out, int out_size) {
    const float* x   = (const float*)d_in[0];
    const int*   ei  = (const int*)d_in[1];     // int32 (JAX default x64-disabled)
    const float* ea  = (const float*)d_in[2];
    const float* We  = (const float*)d_in[3];
    const float* be  = (const float*)d_in[4];
    const float* Ws  = (const float*)d_in[5];
    const float* bs  = (const float*)d_in[6];
    const float* Wt  = (const float*)d_in[7];
    const float* bt  = (const float*)d_in[8];
    const float* W1  = (const float*)d_in[9];
    const float* b1  = (const float*)d_in[10];
    float* out = (float*)d_out;

    const size_t smem1 = (size_t)(128 * 132 + 64 * 132) * 4;                   // ~99 KB
    const size_t smem2 = (size_t)(256 * 68 + 2 * 64 * 72 + 512 + 64 + 16) * 4; // ~109 KB
    cudaFuncSetAttribute(node_proj_kernel, cudaFuncAttributeMaxDynamicSharedMemorySize, (int)smem1);
    cudaFuncSetAttribute(edge_mlp_kernel,  cudaFuncAttributeMaxDynamicSharedMemorySize, (int)smem2);

    node_proj_kernel<<<(NN + 127) / 128, 256, smem1>>>(x, Ws, bs, Wt, bt, be);
    edge_mlp_kernel<<<PGRID, 256, smem2>>>(ea, ei, We, W1, b1, out);
}